// round 15
// baseline (speedup 1.0000x reference)
#include <cuda_runtime.h>
#include <cuda_fp16.h>
#include <cstdint>

#define BB 16
#define HH 128
#define WW 128
#define CC 256
#define KK 32
#define NPIX (HH*WW)
#define NCLS 21
#define BN_EPS 1e-3f

// ---------- encode config ----------
#define TILE_P 64
#define TPB_ENC 512
#define GRID_ENC 148
#define TILES_TOTAL (BB*(NPIX/TILE_P))   // 4096

#define PX2   528
#define PCW2  528
#define PWT2B 80      // wT [p][k] pitch: 64B + 16 pad

// smem layout (bytes)
#define XH0   0
#define XPAR  67584                 // xhi 33792 + xlo 33792 ; x2 buffers
#define CWO   135168                // 16896
#define WT0   152064                // buf(par) = WT0 + par*10240 (whi 5120 + wlo 5120)
#define X2O   172544                // x2(par) = X2O + par*256
#define SMEM_ENC 173056

// ---------------- scratch ----------------
__device__ float g_agg[BB*KK*CC];
__device__ float g_wsum[BB*KK];
__device__ float g_attn[BB*CC];
__device__ float g_c2[KK];
__device__ float g_enc[BB*CC];

// ---------------- helpers ----------------
__device__ __forceinline__ uint32_t smem_u32(const void* p){
    uint32_t a;
    asm("{ .reg .u64 t; cvta.to.shared.u64 t, %1; cvt.u32.u64 %0, t; }" : "=r"(a) : "l"(p));
    return a;
}
__device__ __forceinline__ void ldsm4(uint32_t* r, uint32_t addr){
    asm volatile("ldmatrix.sync.aligned.m8n8.x4.shared.b16 {%0,%1,%2,%3}, [%4];"
        : "=r"(r[0]),"=r"(r[1]),"=r"(r[2]),"=r"(r[3]) : "r"(addr));
}
__device__ __forceinline__ void ldsm4t(uint32_t* r, uint32_t addr){
    asm volatile("ldmatrix.sync.aligned.m8n8.x4.trans.shared.b16 {%0,%1,%2,%3}, [%4];"
        : "=r"(r[0]),"=r"(r[1]),"=r"(r[2]),"=r"(r[3]) : "r"(addr));
}
__device__ __forceinline__ void mmah(float* d,
    uint32_t a0, uint32_t a1, uint32_t a2, uint32_t a3, uint32_t b0, uint32_t b1){
    asm volatile("mma.sync.aligned.m16n8k16.row.col.f32.f16.f16.f32 "
        "{%0,%1,%2,%3}, {%4,%5,%6,%7}, {%8,%9}, {%0,%1,%2,%3};"
        : "+f"(d[0]),"+f"(d[1]),"+f"(d[2]),"+f"(d[3])
        : "r"(a0),"r"(a1),"r"(a2),"r"(a3),"r"(b0),"r"(b1));
}
__device__ __forceinline__ uint32_t pack_h2(float a, float b){
    __half2 h = __floats2half2_rn(a, b);
    return *(uint32_t*)&h;
}
__device__ __forceinline__ uint2 hi2h(float4 v){
    return make_uint2(pack_h2(v.x, v.y), pack_h2(v.z, v.w));
}
__device__ __forceinline__ float4 residual_h(float4 v, uint2 h){
    __half2 a = *(__half2*)&h.x;
    __half2 b = *(__half2*)&h.y;
    return make_float4(v.x - __half2float(a.x), v.y - __half2float(a.y),
                       v.z - __half2float(b.x), v.w - __half2float(b.y));
}
__device__ __forceinline__ void ldg_slot(float4* v, const float* __restrict__ x,
                                         int tile, int s){
    const int pA = s >> 3, j = s & 7;
    const float* src = x + ((size_t)(tile*TILE_P + pA))*CC + j*8;
    #pragma unroll
    for (int i2 = 0; i2 < 4; i2++){
        v[2*i2]   = *(const float4*)(src + i2*64);
        v[2*i2+1] = *(const float4*)(src + i2*64 + 4);
    }
}
__device__ __forceinline__ void convert_slot(char* smem, const float4* v, int par, int s){
    const int pA = s >> 3, j = s & 7;
    char* xh = smem + XH0 + par*XPAR + pA*PX2 + j*16;
    char* xl = xh + 33792;
    float x2v = 0.f;
    #pragma unroll
    for (int i2 = 0; i2 < 4; i2++){
        float4 va = v[2*i2], vb = v[2*i2+1];
        x2v += va.x*va.x + va.y*va.y + va.z*va.z + va.w*va.w;
        x2v += vb.x*vb.x + vb.y*vb.y + vb.z*vb.z + vb.w*vb.w;
        uint2 ha = hi2h(va), hb = hi2h(vb);
        uint2 la = hi2h(residual_h(va, ha)), lb = hi2h(residual_h(vb, hb));
        *(uint4*)(xh + i2*128) = make_uint4(ha.x, ha.y, hb.x, hb.y);
        *(uint4*)(xl + i2*128) = make_uint4(la.x, la.y, lb.x, lb.y);
    }
    x2v += __shfl_xor_sync(0xffffffffu, x2v, 1);
    x2v += __shfl_xor_sync(0xffffffffu, x2v, 2);
    x2v += __shfl_xor_sync(0xffffffffu, x2v, 4);
    if (j == 0) ((float*)(smem + X2O + par*256))[pA] = x2v;
}

// ---------------- init micro-kernels (k_encode stays launch #4) ----------------
__global__ void k_zero0(){
    int t = blockIdx.x*blockDim.x + threadIdx.x;
    ((float4*)g_agg)[t] = make_float4(0.f,0.f,0.f,0.f);
}
__global__ void k_zero1(){
    int t = blockIdx.x*blockDim.x + threadIdx.x;
    ((float4*)g_agg)[16384 + t] = make_float4(0.f,0.f,0.f,0.f);
    if (t < BB*KK) g_wsum[t] = 0.f;
}
__global__ void k_c2(const float* __restrict__ cw){
    int k = blockIdx.x;
    int t = threadIdx.x;
    __shared__ float part[64];
    float v0 = cw[k*CC + t],  v1 = cw[k*CC + t + 64];
    float v2 = cw[k*CC + t + 128], v3 = cw[k*CC + t + 192];
    part[t] = v0*v0 + v1*v1 + v2*v2 + v3*v3;
    __syncthreads();
    if (t < 32){
        float s = part[t] + part[t + 32];
        #pragma unroll
        for (int o = 16; o > 0; o >>= 1) s += __shfl_xor_sync(0xffffffffu, s, o);
        if (t == 0) g_c2[k] = s;
    }
}

// ---------------- fused encode ----------------
__global__ __launch_bounds__(TPB_ENC, 1) void k_encode(
    const float* __restrict__ x,
    const float* __restrict__ cw,
    const float* __restrict__ smo)
{
    extern __shared__ char smem[];
    const uint32_t sb = smem_u32(smem);
    const int t = threadIdx.x;
    const int lane = t & 31;
    const int wid  = t >> 5;
    const int g4 = lane >> 2, t4 = lane & 3;

    {
        const int row = t >> 4, seg = t & 15;
        const float4* crow = (const float4*)(cw + row*CC) + seg*4;
        float4 v0 = crow[0], v1 = crow[1], v2 = crow[2], v3 = crow[3];
        uint2 h0 = hi2h(v0), h1 = hi2h(v1), h2 = hi2h(v2), h3 = hi2h(v3);
        char* hdst = smem + CWO + row*PCW2 + seg*32;
        ((uint4*)hdst)[0] = make_uint4(h0.x,h0.y,h1.x,h1.y);
        ((uint4*)hdst)[1] = make_uint4(h2.x,h2.y,h3.x,h3.y);
    }

    float c2r[8], smr[8];
    if (wid < 4){
        #pragma unroll
        for (int j = 0; j < 8; j++){
            int k = (j >> 1)*8 + t4*2 + (j & 1);
            c2r[j] = g_c2[k]; smr[j] = smo[k];
        }
    }

    float acc[8][4];
    #pragma unroll
    for (int i = 0; i < 8; i++)
        #pragma unroll
        for (int j = 0; j < 4; j++) acc[i][j] = 0.f;
    float wsum_acc[8];
    #pragma unroll
    for (int j = 0; j < 8; j++) wsum_acc[j] = 0.f;

    const int t0 = (int)(((long long)blockIdx.x     * TILES_TOTAL) / GRID_ENC);
    const int t1 = (int)(((long long)(blockIdx.x+1) * TILES_TOTAL) / GRID_ENC);

    // GEMM1 (warps 0-3)
    const uint32_t aoff1 = (uint32_t)(wid*16 + (lane & 15)) * PX2 + (uint32_t)((lane >> 4) * 16);
    const uint32_t boff1 = (uint32_t)((lane & 7) + ((lane >> 4) << 3)) * PCW2
                         + (uint32_t)(((lane >> 3) & 1) * 16);
    // GEMM2 (warps 4-11): mt = k-half, q = col-quarter; all 3 terms per warp
    const int wc = wid - 4;
    const int mt = wc & 1, q = wc >> 1;
    const uint32_t a2base = (uint32_t)(lane & 15)*PWT2B + (uint32_t)((lane >> 4)*16)
                          + (uint32_t)mt*32;
    const uint32_t b2base = (uint32_t)(lane & 15) * PX2 + (uint32_t)((lane >> 4) * 16);
    const int ct = t - 128;

    {
        float4 v[8];
        ldg_slot(v, x, t0, t);
        convert_slot(smem, v, t0 & 1, t);
    }
    __syncthreads();

    for (int tt = t0; tt < t1; tt++){
        const int cur = tt & 1, nxt = cur ^ 1;
        const bool haveNext = (tt + 1 < t1);
        const bool boundary = (tt > t0) && ((tt >> 8) != ((tt - 1) >> 8));
        const int bp = (tt - 1) >> 8;

        if (wid < 4){
            if (boundary){
                float red[8];
                #pragma unroll
                for (int j = 0; j < 8; j++){
                    float s = wsum_acc[j];
                    s += __shfl_xor_sync(0xffffffffu, s, 4);
                    s += __shfl_xor_sync(0xffffffffu, s, 8);
                    s += __shfl_xor_sync(0xffffffffu, s, 16);
                    red[j] = s; wsum_acc[j] = 0.f;
                }
                if (g4 == 0){
                    #pragma unroll
                    for (int j = 0; j < 8; j++){
                        int k = (j >> 1)*8 + t4*2 + (j & 1);
                        atomicAdd(&g_wsum[bp*KK + k], red[j]);
                    }
                }
            }
            // GEMM1
            const uint32_t xhiC = XH0 + (uint32_t)cur*XPAR;
            float d[4][4];
            #pragma unroll
            for (int i = 0; i < 4; i++)
                #pragma unroll
                for (int j = 0; j < 4; j++) d[i][j] = 0.f;
            #pragma unroll 4
            for (int kt = 0; kt < 16; kt++){
                uint32_t a[4], b0[4], b1[4];
                ldsm4(a,  sb + xhiC + aoff1 + kt*32);
                ldsm4(b0, sb + CWO + boff1 + kt*32);
                ldsm4(b1, sb + CWO + boff1 + 16*PCW2 + kt*32);
                mmah(d[0], a[0],a[1],a[2],a[3], b0[0], b0[1]);
                mmah(d[1], a[0],a[1],a[2],a[3], b0[2], b0[3]);
                mmah(d[2], a[0],a[1],a[2],a[3], b1[0], b1[1]);
                mmah(d[3], a[0],a[1],a[2],a[3], b1[2], b1[3]);
            }
            // softmax from fragments
            const int px0 = wid*16 + g4, px1 = px0 + 8;
            const float* x2p = (const float*)(smem + X2O + cur*256);
            const float xa = x2p[px0], xb = x2p[px1];
            float ea[8], eb[8];
            float mxa = -1e30f, mxb = -1e30f;
            #pragma unroll
            for (int j = 0; j < 8; j++){
                int nt = j >> 1, i = j & 1;
                float la = (xa - 2.f*d[nt][i]     + c2r[j]) * smr[j];
                float lb = (xb - 2.f*d[nt][2 + i] + c2r[j]) * smr[j];
                ea[j] = la; eb[j] = lb;
                mxa = fmaxf(mxa, la); mxb = fmaxf(mxb, lb);
            }
            mxa = fmaxf(mxa, __shfl_xor_sync(0xffffffffu, mxa, 1));
            mxa = fmaxf(mxa, __shfl_xor_sync(0xffffffffu, mxa, 2));
            mxb = fmaxf(mxb, __shfl_xor_sync(0xffffffffu, mxb, 1));
            mxb = fmaxf(mxb, __shfl_xor_sync(0xffffffffu, mxb, 2));
            float sa = 0.f, sbv = 0.f;
            #pragma unroll
            for (int j = 0; j < 8; j++){
                ea[j] = __expf(ea[j] - mxa); sa  += ea[j];
                eb[j] = __expf(eb[j] - mxb); sbv += eb[j];
            }
            sa  += __shfl_xor_sync(0xffffffffu, sa, 1);
            sa  += __shfl_xor_sync(0xffffffffu, sa, 2);
            sbv += __shfl_xor_sync(0xffffffffu, sbv, 1);
            sbv += __shfl_xor_sync(0xffffffffu, sbv, 2);
            const float inva = 1.f / sa, invb = 1.f / sbv;
            // wT stored [p][k]: half2 stores at adjacent k pairs
            char* wh = smem + WT0 + cur*10240;
            char* wl = wh + 5120;
            #pragma unroll
            for (int nt = 0; nt < 4; nt++){
                const int k0 = nt*8 + t4*2;
                const int j0 = nt*2, j1 = nt*2 + 1;
                float wa0 = ea[j0]*inva, wa1 = ea[j1]*inva;
                float wb0 = eb[j0]*invb, wb1 = eb[j1]*invb;
                wsum_acc[j0] += wa0 + wb0;
                wsum_acc[j1] += wa1 + wb1;
                __half2 ha = __floats2half2_rn(wa0, wa1);
                __half2 hb = __floats2half2_rn(wb0, wb1);
                *(__half2*)(wh + px0*PWT2B + k0*2) = ha;
                *(__half2*)(wh + px1*PWT2B + k0*2) = hb;
                *(__half2*)(wl + px0*PWT2B + k0*2) =
                    __floats2half2_rn(wa0 - __half2float(ha.x), wa1 - __half2float(ha.y));
                *(__half2*)(wl + px1*PWT2B + k0*2) =
                    __floats2half2_rn(wb0 - __half2float(hb.x), wb1 - __half2float(hb.y));
            }
        } else {
            float4 v[8];
            if (haveNext) ldg_slot(v, x, tt + 1, ct);

            if (wid < 12 && tt > t0){
                // GEMM2(tt-1): all 3 terms, A via ldsm-trans from wT[p][k]
                const uint32_t whp = WT0 + (uint32_t)nxt*10240;
                const uint32_t wlp = whp + 5120;
                const uint32_t xhp = XH0 + (uint32_t)nxt*XPAR;
                const uint32_t xlp = xhp + 33792;
                #pragma unroll
                for (int pt = 0; pt < 4; pt++){
                    uint32_t th[4], tl[4];
                    ldsm4t(th, sb + whp + a2base + pt*16*PWT2B);
                    ldsm4t(tl, sb + wlp + a2base + pt*16*PWT2B);
                    #pragma unroll
                    for (int hf = 0; hf < 4; hf++){
                        const uint32_t boff = b2base + (uint32_t)pt*16*PX2
                                            + (uint32_t)(q*64 + hf*16)*2;
                        uint32_t bh[4], bl[4];
                        ldsm4t(bh, sb + xhp + boff);
                        ldsm4t(bl, sb + xlp + boff);
                        mmah(acc[hf*2],   th[0],th[2],th[1],th[3], bh[0], bh[1]);
                        mmah(acc[hf*2+1], th[0],th[2],th[1],th[3], bh[2], bh[3]);
                        mmah(acc[hf*2],   th[0],th[2],th[1],th[3], bl[0], bl[1]);
                        mmah(acc[hf*2+1], th[0],th[2],th[1],th[3], bl[2], bl[3]);
                        mmah(acc[hf*2],   tl[0],tl[2],tl[1],tl[3], bh[0], bh[1]);
                        mmah(acc[hf*2+1], tl[0],tl[2],tl[1],tl[3], bh[2], bh[3]);
                    }
                }
                if (boundary){
                    const int k1 = mt*16 + g4;
                    #pragma unroll
                    for (int nt = 0; nt < 8; nt++){
                        float* base = g_agg + ((size_t)bp*KK + k1)*CC + q*64 + nt*8 + t4*2;
                        atomicAdd(base,            acc[nt][0]);
                        atomicAdd(base + 1,        acc[nt][1]);
                        atomicAdd(base + 8*CC,     acc[nt][2]);
                        atomicAdd(base + 8*CC + 1, acc[nt][3]);
                        acc[nt][0] = acc[nt][1] = acc[nt][2] = acc[nt][3] = 0.f;
                    }
                }
            }
            asm volatile("bar.sync 3, 384;" ::: "memory");
            if (haveNext){
                convert_slot(smem, v, nxt, ct);
                if (ct < 128){
                    float4 v2[8];
                    ldg_slot(v2, x, tt + 1, ct + 384);
                    convert_slot(smem, v2, nxt, ct + 384);
                }
            }
        }
        __syncthreads();
    }

    // ---- epilogue: GEMM2(t1-1) + final flushes ----
    const int bl2 = (t1 - 1) >> 8;
    if (wid >= 4 && wid < 12){
        const int lp = (t1 - 1) & 1;
        const uint32_t whp = WT0 + (uint32_t)lp*10240;
        const uint32_t wlp = whp + 5120;
        const uint32_t xhp = XH0 + (uint32_t)lp*XPAR;
        const uint32_t xlp = xhp + 33792;
        #pragma unroll
        for (int pt = 0; pt < 4; pt++){
            uint32_t th[4], tl[4];
            ldsm4t(th, sb + whp + a2base + pt*16*PWT2B);
            ldsm4t(tl, sb + wlp + a2base + pt*16*PWT2B);
            #pragma unroll
            for (int hf = 0; hf < 4; hf++){
                const uint32_t boff = b2base + (uint32_t)pt*16*PX2
                                    + (uint32_t)(q*64 + hf*16)*2;
                uint32_t bh[4], bl[4];
                ldsm4t(bh, sb + xhp + boff);
                ldsm4t(bl, sb + xlp + boff);
                mmah(acc[hf*2],   th[0],th[2],th[1],th[3], bh[0], bh[1]);
                mmah(acc[hf*2+1], th[0],th[2],th[1],th[3], bh[2], bh[3]);
                mmah(acc[hf*2],   th[0],th[2],th[1],th[3], bl[0], bl[1]);
                mmah(acc[hf*2+1], th[0],th[2],th[1],th[3], bl[2], bl[3]);
                mmah(acc[hf*2],   tl[0],tl[2],tl[1],tl[3], bh[0], bh[1]);
                mmah(acc[hf*2+1], tl[0],tl[2],tl[1],tl[3], bh[2], bh[3]);
            }
        }
        const int k1 = mt*16 + g4;
        #pragma unroll
        for (int nt = 0; nt < 8; nt++){
            float* base = g_agg + ((size_t)bl2*KK + k1)*CC + q*64 + nt*8 + t4*2;
            atomicAdd(base,            acc[nt][0]);
            atomicAdd(base + 1,        acc[nt][1]);
            atomicAdd(base + 8*CC,     acc[nt][2]);
            atomicAdd(base + 8*CC + 1, acc[nt][3]);
        }
    } else if (wid < 4){
        float red[8];
        #pragma unroll
        for (int j = 0; j < 8; j++){
            float s = wsum_acc[j];
            s += __shfl_xor_sync(0xffffffffu, s, 4);
            s += __shfl_xor_sync(0xffffffffu, s, 8);
            s += __shfl_xor_sync(0xffffffffu, s, 16);
            red[j] = s;
        }
        if (g4 == 0){
            #pragma unroll
            for (int j = 0; j < 8; j++){
                int k = (j >> 1)*8 + t4*2 + (j & 1);
                atomicAdd(&g_wsum[bl2*KK + k], red[j]);
            }
        }
    }
}

// ---------------- heads ----------------
__global__ void k_enc_head(
    const float* __restrict__ cw,
    const float* __restrict__ gamma, const float* __restrict__ beta,
    const float* __restrict__ mean,  const float* __restrict__ var)
{
    const int b = blockIdx.x;
    const int c = blockIdx.y*32 + (threadIdx.x & 31);
    const int kq = threadIdx.x >> 5;
    __shared__ float part[8][33];

    float acc = 0.f;
    #pragma unroll
    for (int kk = 0; kk < 4; kk++){
        int k = kq*4 + kk;
        float a  = g_agg[(b*KK + k)*CC + c] - g_wsum[b*KK + k] * cw[k*CC + c];
        float bn = (a - mean[k]) * rsqrtf(var[k] + BN_EPS) * gamma[k] + beta[k];
        acc += fmaxf(bn, 0.f);
    }
    part[kq][threadIdx.x & 31] = acc;
    __syncthreads();
    if (threadIdx.x < 32){
        float s = part[0][threadIdx.x];
        #pragma unroll
        for (int i = 1; i < 8; i++) s += part[i][threadIdx.x];
        g_enc[b*CC + c] = s;
    }
}

__global__ void k_attn(
    const float* __restrict__ Wenc,  const float* __restrict__ benc,
    const float* __restrict__ Wse,   const float* __restrict__ bse,
    float* __restrict__ out)
{
    const int b = blockIdx.x;
    const int gy = blockIdx.y;
    const int lane = threadIdx.x & 31;
    const int w = threadIdx.x >> 5;
    __shared__ float enc_s[CC];
    __shared__ float part[8][33];

    if (threadIdx.x < CC) enc_s[threadIdx.x] = g_enc[b*CC + threadIdx.x];
    __syncthreads();

    if (gy < 8){
        const int c = gy*32 + lane;
        float s = 0.f;
        #pragma unroll 8
        for (int i = 0; i < 32; i++)
            s += enc_s[w*32 + i] * Wenc[(w*32 + i)*CC + c];
        part[w][lane] = s;
        __syncthreads();
        if (threadIdx.x < 32){
            float acc = benc[gy*32 + threadIdx.x];
            #pragma unroll
            for (int i = 0; i < 8; i++) acc += part[i][threadIdx.x];
            g_attn[b*CC + gy*32 + threadIdx.x] = 1.f / (1.f + __expf(-acc));
        }
    } else {
        const int c = lane;
        float s = 0.f;
        if (c < NCLS){
            #pragma unroll 8
            for (int i = 0; i < 32; i++)
                s += enc_s[w*32 + i] * Wse[(w*32 + i)*NCLS + c];
        }
        part[w][lane] = s;
        __syncthreads();
        if (threadIdx.x < NCLS){
            float acc = bse[threadIdx.x];
            #pragma unroll
            for (int i = 0; i < 8; i++) acc += part[i][threadIdx.x];
            out[(size_t)BB*NPIX*CC + b*NCLS + threadIdx.x] = 1.f / (1.f + __expf(-acc));
        }
    }
}

// ---------------- rescale ----------------
__global__ void k_scale(const float* __restrict__ x, float* __restrict__ out){
    const int F4 = NPIX*CC/4;
    int idx = blockIdx.x*blockDim.x + threadIdx.x;
    int b  = idx / F4;
    int r  = idx - b*F4;
    int c4 = r & 63;
    float4 a = ((const float4*)g_attn)[b*64 + c4];
    float4 v = __ldcs((const float4*)x + idx);
    v.x *= a.x; v.y *= a.y; v.z *= a.z; v.w *= a.w;
    __stcs((float4*)out + idx, v);
}

extern "C" void kernel_launch(void* const* d_in, const int* in_sizes, int n_in,
                              void* d_out, int out_size)
{
    const float* x     = (const float*)d_in[0];
    const float* cw    = (const float*)d_in[1];
    const float* smo   = (const float*)d_in[2];
    const float* gamma = (const float*)d_in[3];
    const float* beta  = (const float*)d_in[4];
    const float* mean  = (const float*)d_in[5];
    const float* var   = (const float*)d_in[6];
    const float* Wenc  = (const float*)d_in[7];
    const float* benc  = (const float*)d_in[8];
    const float* Wse   = (const float*)d_in[9];
    const float* bse   = (const float*)d_in[10];
    float* out = (float*)d_out;

    cudaFuncSetAttribute(k_encode, cudaFuncAttributeMaxDynamicSharedMemorySize, SMEM_ENC);

    k_zero0<<<64, 256>>>();
    k_zero1<<<64, 256>>>();
    k_c2<<<KK, 64>>>(cw);
    k_encode<<<GRID_ENC, TPB_ENC, SMEM_ENC>>>(x, cw, smo);
    k_enc_head<<<dim3(BB, 8), 256>>>(cw, gamma, beta, mean, var);
    k_attn<<<dim3(BB, 9), 256>>>(Wenc, benc, Wse, bse, out);
    k_scale<<<(BB*NPIX*CC/4)/256, 256>>>(x, out);
}